// round 1
// baseline (speedup 1.0000x reference)
#include <cuda_runtime.h>

// Problem constants (fixed shapes from reference)
#define BATCH 8
#define TLEN  4096
#define BC    256
#define RC    64
#define NB0   4
#define NB1   3
#define TB    7           // NB0 + NB1
#define CH0   1024        // x0 channels
#define CH1   768         // x1 channels

// Device-global scratch (allocation-free per harness rules)
__device__ float g_gap[BATCH * BC];
__device__ float g_att[BATCH * TB * BC];

// ---------------------------------------------------------------------------
// Kernel 1: block-sum over channel blocks + global average pool over time.
// grid = BATCH*BC (2048) blocks, 256 threads. Each block reduces 7 rows of
// 4096 floats (fully coalesced float4 loads).
// ---------------------------------------------------------------------------
__global__ void __launch_bounds__(256) gap_kernel(const float* __restrict__ x0,
                                                  const float* __restrict__ x1) {
    const int b = blockIdx.x >> 8;      // / BC
    const int c = blockIdx.x & (BC - 1);
    const int tid = threadIdx.x;

    float acc = 0.0f;

    #pragma unroll
    for (int blk = 0; blk < NB0; ++blk) {
        const float4* row = reinterpret_cast<const float4*>(
            x0 + ((size_t)b * CH0 + (size_t)blk * BC + c) * TLEN);
        #pragma unroll
        for (int i = 0; i < 4; ++i) {
            float4 v = row[tid + i * 256];
            acc += (v.x + v.y) + (v.z + v.w);
        }
    }
    #pragma unroll
    for (int blk = 0; blk < NB1; ++blk) {
        const float4* row = reinterpret_cast<const float4*>(
            x1 + ((size_t)b * CH1 + (size_t)blk * BC + c) * TLEN);
        #pragma unroll
        for (int i = 0; i < 4; ++i) {
            float4 v = row[tid + i * 256];
            acc += (v.x + v.y) + (v.z + v.w);
        }
    }

    // Block reduction
    __shared__ float warpsum[8];
    #pragma unroll
    for (int o = 16; o > 0; o >>= 1)
        acc += __shfl_down_sync(0xffffffffu, acc, o);
    if ((tid & 31) == 0) warpsum[tid >> 5] = acc;
    __syncthreads();
    if (tid < 8) {
        float v = warpsum[tid];
        #pragma unroll
        for (int o = 4; o > 0; o >>= 1)
            v += __shfl_down_sync(0x000000ffu, v, o);
        if (tid == 0) g_gap[b * BC + c] = v * (1.0f / (float)TLEN);
    }
}

// ---------------------------------------------------------------------------
// Kernel 2: h = ReLU(BN(gap @ W1 + b1)); scores = einsum('br,krc->kbc') + bh;
// softmax over k; write att[b][k][c]. Single 512-thread block (tiny work).
// ---------------------------------------------------------------------------
__global__ void __launch_bounds__(512) att_kernel(const float* __restrict__ W1,
                                                  const float* __restrict__ b1,
                                                  const float* __restrict__ gamma,
                                                  const float* __restrict__ beta,
                                                  const float* __restrict__ Wh,
                                                  const float* __restrict__ bh) {
    __shared__ float h_s[BATCH * RC];
    const int tid = threadIdx.x;

    // h: 8*64 = 512 outputs, one per thread
    if (tid < BATCH * RC) {
        const int b = tid / RC;
        const int r = tid % RC;
        float s = b1[r];
        const float* gp = &g_gap[b * BC];
        #pragma unroll 4
        for (int c = 0; c < BC; ++c)
            s = fmaf(gp[c], W1[c * RC + r], s);
        const float bnscale = gamma[r] * rsqrtf(1.0f + 1e-5f);
        h_s[tid] = fmaxf(fmaf(s, bnscale, beta[r]), 0.0f);
    }
    __syncthreads();

    // scores + softmax over k, per (b, c) pair; 2048 pairs / 512 threads = 4 each
    for (int i = tid; i < BATCH * BC; i += 512) {
        const int b = i / BC;
        const int c = i % BC;
        const float* hb = &h_s[b * RC];
        float sc[TB];
        float mx = -1e30f;
        #pragma unroll
        for (int k = 0; k < TB; ++k) {
            float s = bh[k * BC + c];
            const float* w = Wh + (size_t)k * RC * BC + c;
            #pragma unroll 8
            for (int r = 0; r < RC; ++r)
                s = fmaf(hb[r], w[(size_t)r * BC], s);
            sc[k] = s;
            mx = fmaxf(mx, s);
        }
        float sum = 0.0f;
        #pragma unroll
        for (int k = 0; k < TB; ++k) { sc[k] = expf(sc[k] - mx); sum += sc[k]; }
        const float inv = 1.0f / sum;
        #pragma unroll
        for (int k = 0; k < TB; ++k)
            g_att[(b * TB + k) * BC + c] = sc[k] * inv;
    }
}

// ---------------------------------------------------------------------------
// Kernel 3: streaming scale. One block per channel-row (16 KB), float4 I/O.
// Output layout: out0 (B*1024*T) followed by out1 (B*768*T).
// ---------------------------------------------------------------------------
__global__ void __launch_bounds__(256) scale_kernel(const float* __restrict__ x0,
                                                    const float* __restrict__ x1,
                                                    float* __restrict__ out) {
    const int bid = blockIdx.x;
    const int tid = threadIdx.x;

    const float* src;
    float* dst;
    int b, ch, kblk;
    if (bid < BATCH * CH0) {
        b = bid >> 10;            // / CH0
        ch = bid & (CH0 - 1);
        src = x0 + (size_t)bid * TLEN;
        dst = out + (size_t)bid * TLEN;
        kblk = ch >> 8;
    } else {
        const int r = bid - BATCH * CH0;
        b = r / CH1;
        ch = r % CH1;
        src = x1 + (size_t)r * TLEN;
        dst = out + (size_t)BATCH * CH0 * TLEN + (size_t)r * TLEN;
        kblk = NB0 + (ch >> 8);
    }

    const float a = g_att[(b * TB + kblk) * BC + (ch & (BC - 1))];

    const float4* s4 = reinterpret_cast<const float4*>(src);
    float4* d4 = reinterpret_cast<float4*>(dst);
    #pragma unroll
    for (int i = 0; i < 4; ++i) {
        float4 v = s4[tid + i * 256];
        v.x *= a; v.y *= a; v.z *= a; v.w *= a;
        d4[tid + i * 256] = v;
    }
}

// ---------------------------------------------------------------------------
extern "C" void kernel_launch(void* const* d_in, const int* in_sizes, int n_in,
                              void* d_out, int out_size) {
    const float* x0    = (const float*)d_in[0];  // [8,1024,4096]
    const float* x1    = (const float*)d_in[1];  // [8,768,4096]
    const float* W1    = (const float*)d_in[2];  // [256,64]
    const float* b1    = (const float*)d_in[3];  // [64]
    const float* gamma = (const float*)d_in[4];  // [64]
    const float* beta  = (const float*)d_in[5];  // [64]
    const float* Wh    = (const float*)d_in[6];  // [7,64,256]
    const float* bh    = (const float*)d_in[7];  // [7,256]
    float* out = (float*)d_out;

    gap_kernel<<<BATCH * BC, 256>>>(x0, x1);
    att_kernel<<<1, 512>>>(W1, b1, gamma, beta, Wh, bh);
    scale_kernel<<<BATCH * (CH0 + CH1), 256>>>(x0, x1, out);
}

// round 2
// speedup vs baseline: 1.9878x; 1.9878x over previous
#include <cuda_runtime.h>

// Problem constants (fixed shapes from reference)
#define BATCH 8
#define TLEN  4096
#define BC    256
#define RC    64
#define NB0   4
#define NB1   3
#define TB    7           // NB0 + NB1
#define CH0   1024        // x0 channels
#define CH1   768         // x1 channels

// Device-global scratch (allocation-free per harness rules)
__device__ float g_gap[BATCH * BC];
__device__ float g_h[BATCH * RC];
__device__ float g_att[BATCH * TB * BC];

// ---------------------------------------------------------------------------
// Kernel 1: block-sum over channel blocks + global average pool over time.
// grid = BATCH*BC (2048) blocks, 256 threads. Streaming loads (single use).
// ---------------------------------------------------------------------------
__global__ void __launch_bounds__(256) gap_kernel(const float* __restrict__ x0,
                                                  const float* __restrict__ x1) {
    const int b = blockIdx.x >> 8;      // / BC
    const int c = blockIdx.x & (BC - 1);
    const int tid = threadIdx.x;

    float acc = 0.0f;

    #pragma unroll
    for (int blk = 0; blk < NB0; ++blk) {
        const float4* row = reinterpret_cast<const float4*>(
            x0 + ((size_t)b * CH0 + (size_t)blk * BC + c) * TLEN);
        #pragma unroll
        for (int i = 0; i < 4; ++i) {
            float4 v = __ldcs(row + tid + i * 256);
            acc += (v.x + v.y) + (v.z + v.w);
        }
    }
    #pragma unroll
    for (int blk = 0; blk < NB1; ++blk) {
        const float4* row = reinterpret_cast<const float4*>(
            x1 + ((size_t)b * CH1 + (size_t)blk * BC + c) * TLEN);
        #pragma unroll
        for (int i = 0; i < 4; ++i) {
            float4 v = __ldcs(row + tid + i * 256);
            acc += (v.x + v.y) + (v.z + v.w);
        }
    }

    // Block reduction
    __shared__ float warpsum[8];
    #pragma unroll
    for (int o = 16; o > 0; o >>= 1)
        acc += __shfl_down_sync(0xffffffffu, acc, o);
    if ((tid & 31) == 0) warpsum[tid >> 5] = acc;
    __syncthreads();
    if (tid < 8) {
        float v = warpsum[tid];
        #pragma unroll
        for (int o = 4; o > 0; o >>= 1)
            v += __shfl_down_sync(0x000000ffu, v, o);
        if (tid == 0) g_gap[b * BC + c] = v * (1.0f / (float)TLEN);
    }
}

// ---------------------------------------------------------------------------
// Kernel 2a: h = ReLU(BN(gap @ W1 + b1)).  512 outputs, one block.
// ---------------------------------------------------------------------------
__global__ void __launch_bounds__(512) h_kernel(const float* __restrict__ W1,
                                                const float* __restrict__ b1,
                                                const float* __restrict__ gamma,
                                                const float* __restrict__ beta) {
    const int tid = threadIdx.x;
    const int b = tid >> 6;          // / RC
    const int r = tid & (RC - 1);
    float s = b1[r];
    const float* gp = &g_gap[b * BC];
    #pragma unroll 8
    for (int c = 0; c < BC; ++c)
        s = fmaf(gp[c], W1[c * RC + r], s);
    const float bnscale = gamma[r] * rsqrtf(1.0f + 1e-5f);
    g_h[tid] = fmaxf(fmaf(s, bnscale, beta[r]), 0.0f);
}

// ---------------------------------------------------------------------------
// Kernel 2b: scores = einsum('br,krc->kbc') + bh; softmax over k.
// 16 blocks x 128 threads = 2048 threads, one per (b,c). Coalesced Wh reads.
// ---------------------------------------------------------------------------
__global__ void __launch_bounds__(128) att_kernel(const float* __restrict__ Wh,
                                                  const float* __restrict__ bh) {
    const int i = blockIdx.x * 128 + threadIdx.x;   // 0..2047
    const int b = i >> 8;            // / BC
    const int c = i & (BC - 1);

    // Load h row into registers (broadcast within warp: same b across 32 lanes? b
    // changes every 256 threads, so uniform per warp — L1-resident loads)
    float hb[RC];
    #pragma unroll
    for (int r = 0; r < RC; ++r) hb[r] = g_h[b * RC + r];

    float sc[TB];
    float mx = -1e30f;
    #pragma unroll
    for (int k = 0; k < TB; ++k) {
        float s = bh[k * BC + c];
        const float* w = Wh + (size_t)k * RC * BC + c;
        #pragma unroll 16
        for (int r = 0; r < RC; ++r)
            s = fmaf(hb[r], w[(size_t)r * BC], s);
        sc[k] = s;
        mx = fmaxf(mx, s);
    }
    float sum = 0.0f;
    #pragma unroll
    for (int k = 0; k < TB; ++k) { sc[k] = __expf(sc[k] - mx); sum += sc[k]; }
    const float inv = 1.0f / sum;
    #pragma unroll
    for (int k = 0; k < TB; ++k)
        g_att[(b * TB + k) * BC + c] = sc[k] * inv;
}

// ---------------------------------------------------------------------------
// Kernel 3: streaming scale. One block per channel-row (16 KB), float4 I/O,
// evict-first loads and stores (single-use data).
// ---------------------------------------------------------------------------
__global__ void __launch_bounds__(256) scale_kernel(const float* __restrict__ x0,
                                                    const float* __restrict__ x1,
                                                    float* __restrict__ out) {
    const int bid = blockIdx.x;
    const int tid = threadIdx.x;

    const float* src;
    float* dst;
    int b, ch, kblk;
    if (bid < BATCH * CH0) {
        b = bid >> 10;            // / CH0
        ch = bid & (CH0 - 1);
        src = x0 + (size_t)bid * TLEN;
        dst = out + (size_t)bid * TLEN;
        kblk = ch >> 8;
    } else {
        const int r = bid - BATCH * CH0;
        b = r / CH1;
        ch = r % CH1;
        src = x1 + (size_t)r * TLEN;
        dst = out + (size_t)BATCH * CH0 * TLEN + (size_t)r * TLEN;
        kblk = NB0 + (ch >> 8);
    }

    const float a = g_att[(b * TB + kblk) * BC + (ch & (BC - 1))];

    const float4* s4 = reinterpret_cast<const float4*>(src);
    float4* d4 = reinterpret_cast<float4*>(dst);
    float4 v[4];
    #pragma unroll
    for (int i = 0; i < 4; ++i)
        v[i] = __ldcs(s4 + tid + i * 256);
    #pragma unroll
    for (int i = 0; i < 4; ++i) {
        v[i].x *= a; v[i].y *= a; v[i].z *= a; v[i].w *= a;
        __stcs(d4 + tid + i * 256, v[i]);
    }
}

// ---------------------------------------------------------------------------
extern "C" void kernel_launch(void* const* d_in, const int* in_sizes, int n_in,
                              void* d_out, int out_size) {
    const float* x0    = (const float*)d_in[0];  // [8,1024,4096]
    const float* x1    = (const float*)d_in[1];  // [8,768,4096]
    const float* W1    = (const float*)d_in[2];  // [256,64]
    const float* b1    = (const float*)d_in[3];  // [64]
    const float* gamma = (const float*)d_in[4];  // [64]
    const float* beta  = (const float*)d_in[5];  // [64]
    const float* Wh    = (const float*)d_in[6];  // [7,64,256]
    const float* bh    = (const float*)d_in[7];  // [7,256]
    float* out = (float*)d_out;

    gap_kernel<<<BATCH * BC, 256>>>(x0, x1);
    h_kernel<<<1, 512>>>(W1, b1, gamma, beta);
    att_kernel<<<16, 128>>>(Wh, bh);
    scale_kernel<<<BATCH * (CH0 + CH1), 256>>>(x0, x1, out);
}